// round 16
// baseline (speedup 1.0000x reference)
#include <cuda_runtime.h>
#include <cuda_bf16.h>
#include <cuda_fp16.h>
#include <cstdint>
#include <math.h>

// Problem constants
constexpr int Bz  = 4;
constexpr int Sq  = 1024;
constexpr int DIM = 4096;
constexpr int Hh  = 32;
constexpr int HD  = 128;
constexpr int MM  = Bz * Sq;        // 4096 rows
constexpr float QS2 = 0.08838834764831845f * 1.4426950408889634f; // 1/sqrt(128)*log2(e)

// Scratch (static device globals)
__device__ __half g_xh[MM * DIM];
__device__ __half g_wqh[DIM * DIM];
__device__ __half g_wkh[DIM * DIM];
__device__ __half g_wvh[DIM * DIM];
__device__ __half g_woh[DIM * DIM];
__device__ __half g_atth[MM * DIM];
__device__ __half g_qh[MM * DIM];
__device__ __half g_kh[MM * DIM];
__device__ __half g_vh[MM * DIM];

// ---------------------------------------------------------------------------
// helpers
// ---------------------------------------------------------------------------
__device__ __forceinline__ uint32_t smem_u32(const void* p) {
    uint32_t a;
    asm("{ .reg .u64 t; cvta.to.shared.u64 t, %1; cvt.u32.u64 %0, t; }"
        : "=r"(a) : "l"(p));
    return a;
}
__device__ __forceinline__ void ldsm4(uint32_t* r, uint32_t addr) {
    asm volatile("ldmatrix.sync.aligned.m8n8.x4.shared.b16 {%0,%1,%2,%3}, [%4];"
        : "=r"(r[0]), "=r"(r[1]), "=r"(r[2]), "=r"(r[3]) : "r"(addr));
}
__device__ __forceinline__ void ldsm4t(uint32_t* r, uint32_t addr) {
    asm volatile("ldmatrix.sync.aligned.m8n8.x4.trans.shared.b16 {%0,%1,%2,%3}, [%4];"
        : "=r"(r[0]), "=r"(r[1]), "=r"(r[2]), "=r"(r[3]) : "r"(addr));
}
__device__ __forceinline__ void mma_f16(float* d, const uint32_t* a,
                                        uint32_t b0, uint32_t b1) {
    asm volatile(
        "mma.sync.aligned.m16n8k16.row.col.f32.f16.f16.f32 "
        "{%0,%1,%2,%3}, {%4,%5,%6,%7}, {%8,%9}, {%0,%1,%2,%3};"
        : "+f"(d[0]), "+f"(d[1]), "+f"(d[2]), "+f"(d[3])
        : "r"(a[0]), "r"(a[1]), "r"(a[2]), "r"(a[3]), "r"(b0), "r"(b1));
}
__device__ __forceinline__ float fexp2(float x) {
    float y;
    asm("ex2.approx.ftz.f32 %0, %1;" : "=f"(y) : "f"(x));
    return y;
}
__device__ __forceinline__ uint32_t packh2(float a, float b) {
    __half2 h = __floats2half2_rn(a, b);
    return *(uint32_t*)&h;
}

// ---------------------------------------------------------------------------
// fused fp32 -> fp16 conversion for 5 tensors, 1 launch, 8 elems/thread.
// ---------------------------------------------------------------------------
__global__ __launch_bounds__(256)
void cvt_all(const float* __restrict__ s0, const float* __restrict__ s1,
             const float* __restrict__ s2, const float* __restrict__ s3,
             const float* __restrict__ s4,
             __half* __restrict__ d0, __half* __restrict__ d1,
             __half* __restrict__ d2, __half* __restrict__ d3,
             __half* __restrict__ d4)
{
    const int seg = blockIdx.x >> 13;
    const int blk = blockIdx.x & 8191;
    const float* s = (seg == 0) ? s0 : (seg == 1) ? s1 : (seg == 2) ? s2
                    : (seg == 3) ? s3 : s4;
    __half* d = (seg == 0) ? d0 : (seg == 1) ? d1 : (seg == 2) ? d2
               : (seg == 3) ? d3 : d4;
    const long i = ((long)blk * 256 + threadIdx.x) * 4;
    const long j = i + 8192 * 256 * 4;
    float4 v0 = *(const float4*)(s + i);
    float4 v1 = *(const float4*)(s + j);
    *(__half2*)(d + i)     = __floats2half2_rn(v0.x, v0.y);
    *(__half2*)(d + i + 2) = __floats2half2_rn(v0.z, v0.w);
    *(__half2*)(d + j)     = __floats2half2_rn(v1.x, v1.y);
    *(__half2*)(d + j + 2) = __floats2half2_rn(v1.z, v1.w);
}

// ---------------------------------------------------------------------------
// GEMM core: CTA 128x64 (halved N-tile to cut wave-quantization tail),
// BK=32, 8 warps (2m x 4n), warp tile 64x16, ldmatrix.x4,
// 4-stage cp.async, 2 CTAs/SM, one barrier per k-tile.
// ---------------------------------------------------------------------------
constexpr int BM = 128, BN = 64, BK = 32, KPAD = 40;
constexpr int A_E = BM * KPAD;                 // 5120
constexpr int B_E = BN * KPAD;                 // 2560
constexpr int STAGE_E = A_E + B_E;             // 7680 elems = 15KB
constexpr int GEMM_SMEM = 4 * STAGE_E * 2;     // 61440 bytes

struct GemmCore {
    template<typename EPI>
    __device__ __forceinline__ static void run(
        const __half* Ag, const __half* Wg, char* shraw, EPI&& epi)
    {
        const uint32_t smb = smem_u32(shraw);
        const int tid  = threadIdx.x;
        const int wid  = tid >> 5;
        const int lane = tid & 31;
        const int warp_m = wid & 1;    // 64 rows
        const int warp_n = wid >> 1;   // 16 cols

        auto issue = [&](int kt, int st) {
            const long kof = (long)kt * BK;
            const uint32_t sbase = smb + (uint32_t)(st * STAGE_E) * 2;
#pragma unroll
            for (int q = 0; q < 2; q++) {          // A: 512 uint4
                const int c = tid + 256 * q;
                const int row = c >> 2, cc = (c & 3) * 8;
                const __half* s = Ag + (long)row * DIM + kof + cc;
                const uint32_t d = sbase + (uint32_t)(row * KPAD + cc) * 2;
                asm volatile("cp.async.cg.shared.global [%0], [%1], 16;" :: "r"(d), "l"(s));
            }
            {                                       // B: 256 uint4
                const int c = tid;
                const int row = c >> 2, cc = (c & 3) * 8;
                const __half* s = Wg + (long)row * DIM + kof + cc;
                const uint32_t d = sbase + (uint32_t)(A_E + row * KPAD + cc) * 2;
                asm volatile("cp.async.cg.shared.global [%0], [%1], 16;" :: "r"(d), "l"(s));
            }
        };

        float acc[4][2][4];
#pragma unroll
        for (int i = 0; i < 4; i++)
#pragma unroll
            for (int j = 0; j < 2; j++)
#pragma unroll
                for (int q = 0; q < 4; q++) acc[i][j][q] = 0.f;

        issue(0, 0); asm volatile("cp.async.commit_group;" ::: "memory");
        issue(1, 1); asm volatile("cp.async.commit_group;" ::: "memory");
        issue(2, 2); asm volatile("cp.async.commit_group;" ::: "memory");

        const int arow  = warp_m * 64 + (lane & 15);
        const int acol8 = (lane >> 4) << 3;
        const int brow  = warp_n * 16 + (lane & 7) + ((lane >> 4) << 3);
        const int bcol8 = ((lane >> 3) & 1) << 3;

        const int NT = DIM / BK;   // 128
        for (int t = 0; t < NT; t++) {
            asm volatile("cp.async.wait_group 2;" ::: "memory");
            __syncthreads();

            if (t + 3 < NT) issue(t + 3, (t + 3) & 3);
            asm volatile("cp.async.commit_group;" ::: "memory");

            const uint32_t base = smb + (uint32_t)((t & 3) * STAGE_E) * 2;
#pragma unroll
            for (int ks = 0; ks < 2; ks++) {
                const int kk = ks * 16;
                uint32_t af[4][4], bf[4];
#pragma unroll
                for (int mf = 0; mf < 4; mf++)
                    ldsm4(af[mf], base + (uint32_t)((arow + mf * 16) * KPAD + kk + acol8) * 2);
                ldsm4(bf, base + (uint32_t)(A_E + brow * KPAD + kk + bcol8) * 2);
#pragma unroll
                for (int mf = 0; mf < 4; mf++) {
                    mma_f16(acc[mf][0], af[mf], bf[0], bf[1]);
                    mma_f16(acc[mf][1], af[mf], bf[2], bf[3]);
                }
            }
        }
        epi(acc, warp_m, warp_n, lane);
    }
};

// ---------------------------------------------------------------------------
// Fused QKV GEMM: tiles = 32 m x (3*64) n = 6144 CTAs.
// n-third selects weight + epilogue.
// ---------------------------------------------------------------------------
__global__ __launch_bounds__(256, 2)
void tc_gemm_qkv(const __half* __restrict__ A,
                 const __half* __restrict__ Wq, const __half* __restrict__ Wk,
                 const __half* __restrict__ Wv,
                 __half* __restrict__ qo, __half* __restrict__ ko,
                 __half* __restrict__ vo,
                 const float* __restrict__ fcos, const float* __restrict__ fsin)
{
    extern __shared__ __align__(16) char shraw[];

    // raster: groups of 8 m-tiles sweep all 192 n-tiles
    const int bid = blockIdx.x;
    const int grp = bid / (8 * 192);
    const int r   = bid - grp * (8 * 192);
    const int m0  = (grp * 8 + (r & 7)) * BM;
    const int nidx = r >> 3;              // 0..191
    const int third = nidx >> 6;          // 0=q 1=k 2=v
    const int n0   = (nidx & 63) * BN;

    const __half* W = (third == 0) ? Wq : (third == 1) ? Wk : Wv;
    __half* O = (third == 0) ? qo : (third == 1) ? ko : vo;

    GemmCore::run(A + (long)m0 * DIM, W + (long)n0 * DIM, shraw,
        [&](float acc[4][2][4], int warp_m, int warp_n, int lane) {
            const int g   = lane >> 2;
            const int tig = lane & 3;
#pragma unroll
            for (int mf = 0; mf < 4; mf++) {
                const long gr0 = m0 + warp_m * 64 + mf * 16 + g;
#pragma unroll
                for (int nf = 0; nf < 2; nf++) {
                    const int gc = n0 + warp_n * 16 + nf * 8 + tig * 2;
#pragma unroll
                    for (int half = 0; half < 2; half++) {
                        const long row = gr0 + half * 8;
                        float v0 = acc[mf][nf][2 * half], v1 = acc[mf][nf][2 * half + 1];
                        float o0, o1;
                        if (third <= 1) {
                            const int s = (int)(row & (Sq - 1));
                            const int p = (gc & (HD - 1)) >> 1;
                            const float c  = fcos[s * 64 + p];
                            const float sn = fsin[s * 64 + p];
                            o0 = v0 * c - v1 * sn;
                            o1 = v0 * sn + v1 * c;
                            if (third == 0) { o0 *= QS2; o1 *= QS2; }
                        } else {
                            o0 = v0; o1 = v1;
                        }
                        *(__half2*)(O + row * DIM + gc) = __floats2half2_rn(o0, o1);
                    }
                }
            }
        });
}

// ---------------------------------------------------------------------------
// Output GEMM: tiles = 32 m x 64 n = 2048 CTAs, fp32 store.
// ---------------------------------------------------------------------------
__global__ __launch_bounds__(256, 2)
void tc_gemm_o(const __half* __restrict__ A, const __half* __restrict__ W,
               float* __restrict__ C)
{
    extern __shared__ __align__(16) char shraw[];

    // raster: groups of 4 m-tiles sweep all 64 n-tiles
    const int bid = blockIdx.x;
    const int grp = bid >> 8;             // / 256
    const int r   = bid & 255;
    const int m0  = (grp * 4 + (r & 3)) * BM;
    const int n0  = (r >> 2) * BN;

    GemmCore::run(A + (long)m0 * DIM, W + (long)n0 * DIM, shraw,
        [&](float acc[4][2][4], int warp_m, int warp_n, int lane) {
            const int g   = lane >> 2;
            const int tig = lane & 3;
#pragma unroll
            for (int mf = 0; mf < 4; mf++) {
                const long gr0 = m0 + warp_m * 64 + mf * 16 + g;
#pragma unroll
                for (int nf = 0; nf < 2; nf++) {
                    const int gc = n0 + warp_n * 16 + nf * 8 + tig * 2;
                    *(float2*)(C + gr0 * DIM + gc)       = make_float2(acc[mf][nf][0], acc[mf][nf][1]);
                    *(float2*)(C + (gr0 + 8) * DIM + gc) = make_float2(acc[mf][nf][2], acc[mf][nf][3]);
                }
            }
        });
}

// ---------------------------------------------------------------------------
// Flash attention, single-pass fp16, register-resident P,
// double-buffered cp.async K/V.  Q block 128, KV 64.
// Smem: Q + 2*(K+V) = 104448 B -> 2 CTAs/SM.
// ---------------------------------------------------------------------------
constexpr int QP = 136;
constexpr int O_Q  = 0;
constexpr int O_K0 = O_Q  + 128 * QP;
constexpr int O_V0 = O_K0 + 64 * QP;
constexpr int O_K1 = O_V0 + 64 * QP;
constexpr int O_V1 = O_K1 + 64 * QP;
constexpr int ATTN_SMEM = (O_V1 + 64 * QP) * 2;   // 104448 bytes

__global__ __launch_bounds__(256, 2)
void attn_mma(const __half* __restrict__ Qg, const __half* __restrict__ Kg,
              const __half* __restrict__ Vg, __half* __restrict__ Oh)
{
    extern __shared__ __align__(16) __half sb[];
    const uint32_t smb = smem_u32(sb);

    const int tid  = threadIdx.x;
    const int w    = tid >> 5;
    const int lane = tid & 31;
    const int g    = lane >> 2;
    const int tig  = lane & 3;

    const int qb = blockIdx.x;
    const int bh = blockIdx.y;
    const int b  = bh >> 5;
    const int h  = bh & (Hh - 1);
    const int rowbase = b * Sq + qb * 128;
    const long colbase = h * HD;

    auto issue_kv = [&](int kb, int buf) {
        const long rbase = (long)(b * Sq + kb * 64);
        const uint32_t kdst = smb + (uint32_t)((buf ? O_K1 : O_K0)) * 2;
        const uint32_t vdst = smb + (uint32_t)((buf ? O_V1 : O_V0)) * 2;
#pragma unroll
        for (int q = 0; q < 4; q++) {
            const int u = tid + 256 * q;
            const int rr = u >> 4, c8 = (u & 15) * 8;
            const __half* ks = Kg + (rbase + rr) * DIM + colbase + c8;
            const __half* vs = Vg + (rbase + rr) * DIM + colbase + c8;
            const uint32_t off = (uint32_t)(rr * QP + c8) * 2;
            asm volatile("cp.async.cg.shared.global [%0], [%1], 16;" :: "r"(kdst + off), "l"(ks));
            asm volatile("cp.async.cg.shared.global [%0], [%1], 16;" :: "r"(vdst + off), "l"(vs));
        }
    };

    // ---- load Q tile (128 x 128 fp16) ----
#pragma unroll
    for (int q = 0; q < 8; q++) {
        const int u = tid + 256 * q;
        const int rr = u >> 4, c8 = (u & 15) * 8;
        uint4 v = *(const uint4*)(Qg + (long)(rowbase + rr) * DIM + colbase + c8);
        *(uint4*)(sb + O_Q + rr * QP + c8) = v;
    }
    issue_kv(0, 0);
    asm volatile("cp.async.commit_group;" ::: "memory");
    __syncthreads();

    // ---- preload Q fragments ----
    uint32_t qf[8][4];
    {
        const int rowQ = w * 16 + (lane & 15);
        const int colH = (lane >> 4) << 3;
#pragma unroll
        for (int ks = 0; ks < 8; ks++)
            ldsm4(qf[ks], smb + (uint32_t)(O_Q + rowQ * QP + ks * 16 + colH) * 2);
    }

    float o[16][4];
#pragma unroll
    for (int i = 0; i < 16; i++)
#pragma unroll
        for (int q = 0; q < 4; q++) o[i][q] = 0.f;
    float m0 = -1e30f, m1 = -1e30f, l0 = 0.f, l1 = 0.f;

    const int browK = (lane & 7) + ((lane >> 4) << 3);
    const int bcol8 = ((lane >> 3) & 1) << 3;
    const int vrow  = (lane & 7) + (((lane >> 3) & 1) << 3);
    const int vcol8 = (lane >> 4) << 3;

    const int nkb = 2 * qb + 2;
    for (int kb = 0; kb < nkb; kb++) {
        __syncthreads();

        if (kb + 1 < nkb) issue_kv(kb + 1, (kb + 1) & 1);
        asm volatile("cp.async.commit_group;" ::: "memory");
        asm volatile("cp.async.wait_group 1;" ::: "memory");
        __syncthreads();

        const uint32_t O_K = (kb & 1) ? O_K1 : O_K0;
        const uint32_t O_V = (kb & 1) ? O_V1 : O_V0;

        // ---- S = Q K^T ----
        float s[8][4];
#pragma unroll
        for (int i = 0; i < 8; i++)
#pragma unroll
            for (int q = 0; q < 4; q++) s[i][q] = 0.f;

#pragma unroll
        for (int ks = 0; ks < 8; ks++) {
#pragma unroll
            for (int nfp = 0; nfp < 4; nfp++) {
                uint32_t kf[4];
                ldsm4(kf, smb + (uint32_t)(O_K + (browK + nfp * 16) * QP + ks * 16 + bcol8) * 2);
                mma_f16(s[2 * nfp],     qf[ks], kf[0], kf[1]);
                mma_f16(s[2 * nfp + 1], qf[ks], kf[2], kf[3]);
            }
        }

        // ---- causal mask ----
        const int r0g = qb * 128 + w * 16 + g;
        if (kb * 64 + 63 > r0g) {
            const int r1g = r0g + 8;
#pragma unroll
            for (int nf = 0; nf < 8; nf++) {
                const int c0 = kb * 64 + nf * 8 + tig * 2;
                if (c0 > r0g)     s[nf][0] = -1e30f;
                if (c0 + 1 > r0g) s[nf][1] = -1e30f;
                if (c0 > r1g)     s[nf][2] = -1e30f;
                if (c0 + 1 > r1g) s[nf][3] = -1e30f;
            }
        }

        // ---- online softmax (base-2) ----
        float rm0 = -1e30f, rm1 = -1e30f;
#pragma unroll
        for (int nf = 0; nf < 8; nf++) {
            rm0 = fmaxf(rm0, fmaxf(s[nf][0], s[nf][1]));
            rm1 = fmaxf(rm1, fmaxf(s[nf][2], s[nf][3]));
        }
        rm0 = fmaxf(rm0, __shfl_xor_sync(0xffffffffu, rm0, 1));
        rm0 = fmaxf(rm0, __shfl_xor_sync(0xffffffffu, rm0, 2));
        rm1 = fmaxf(rm1, __shfl_xor_sync(0xffffffffu, rm1, 1));
        rm1 = fmaxf(rm1, __shfl_xor_sync(0xffffffffu, rm1, 2));

        const float mn0 = fmaxf(m0, rm0), mn1 = fmaxf(m1, rm1);
        const float sc0 = fexp2(m0 - mn0), sc1 = fexp2(m1 - mn1);
        m0 = mn0; m1 = mn1;

        float rs0 = 0.f, rs1 = 0.f;
#pragma unroll
        for (int nf = 0; nf < 8; nf++) {
            s[nf][0] = fexp2(s[nf][0] - mn0);
            s[nf][1] = fexp2(s[nf][1] - mn0);
            s[nf][2] = fexp2(s[nf][2] - mn1);
            s[nf][3] = fexp2(s[nf][3] - mn1);
            rs0 += s[nf][0] + s[nf][1];
            rs1 += s[nf][2] + s[nf][3];
        }
        rs0 += __shfl_xor_sync(0xffffffffu, rs0, 1);
        rs0 += __shfl_xor_sync(0xffffffffu, rs0, 2);
        rs1 += __shfl_xor_sync(0xffffffffu, rs1, 1);
        rs1 += __shfl_xor_sync(0xffffffffu, rs1, 2);
        l0 = l0 * sc0 + rs0;
        l1 = l1 * sc1 + rs1;

#pragma unroll
        for (int nf = 0; nf < 16; nf++) {
            o[nf][0] *= sc0; o[nf][1] *= sc0;
            o[nf][2] *= sc1; o[nf][3] *= sc1;
        }

        // ---- pack P into A-fragments in registers ----
        uint32_t pf[4][4];
#pragma unroll
        for (int ks2 = 0; ks2 < 4; ks2++) {
            pf[ks2][0] = packh2(s[2 * ks2][0],     s[2 * ks2][1]);
            pf[ks2][1] = packh2(s[2 * ks2][2],     s[2 * ks2][3]);
            pf[ks2][2] = packh2(s[2 * ks2 + 1][0], s[2 * ks2 + 1][1]);
            pf[ks2][3] = packh2(s[2 * ks2 + 1][2], s[2 * ks2 + 1][3]);
        }

        // ---- O += P V ----
#pragma unroll
        for (int ks2 = 0; ks2 < 4; ks2++) {
#pragma unroll
            for (int nfp = 0; nfp < 8; nfp++) {
                uint32_t vf[4];
                ldsm4t(vf, smb + (uint32_t)(O_V + (vrow + ks2 * 16) * QP + nfp * 16 + vcol8) * 2);
                mma_f16(o[2 * nfp],     pf[ks2], vf[0], vf[1]);
                mma_f16(o[2 * nfp + 1], pf[ks2], vf[2], vf[3]);
            }
        }
    }

    // ---- epilogue ----
    const float inv0 = 1.f / l0, inv1 = 1.f / l1;
    const long gr0 = rowbase + w * 16 + g;
#pragma unroll
    for (int nf = 0; nf < 16; nf++) {
        const long gc = colbase + nf * 8 + tig * 2;
        *(__half2*)(Oh + gr0 * DIM + gc) =
            __floats2half2_rn(o[nf][0] * inv0, o[nf][1] * inv0);
        *(__half2*)(Oh + (gr0 + 8) * DIM + gc) =
            __floats2half2_rn(o[nf][2] * inv1, o[nf][3] * inv1);
    }
}

// ---------------------------------------------------------------------------
// Launch:  cvt_all -> fused qkv GEMM -> attention -> wo GEMM  (4 launches)
// ---------------------------------------------------------------------------
extern "C" void kernel_launch(void* const* d_in, const int* in_sizes, int n_in,
                              void* d_out, int out_size)
{
    const float* x    = (const float*)d_in[0];
    const float* fcos = (const float*)d_in[2];
    const float* fsin = (const float*)d_in[3];
    const float* wq   = (const float*)d_in[5];
    const float* wk   = (const float*)d_in[6];
    const float* wv   = (const float*)d_in[7];
    const float* wo   = (const float*)d_in[8];
    float* out = (float*)d_out;

    __half *xh, *wqh, *wkh, *wvh, *woh, *atth, *qh, *kh, *vh;
    cudaGetSymbolAddress((void**)&xh,   g_xh);
    cudaGetSymbolAddress((void**)&wqh,  g_wqh);
    cudaGetSymbolAddress((void**)&wkh,  g_wkh);
    cudaGetSymbolAddress((void**)&wvh,  g_wvh);
    cudaGetSymbolAddress((void**)&woh,  g_woh);
    cudaGetSymbolAddress((void**)&atth, g_atth);
    cudaGetSymbolAddress((void**)&qh,   g_qh);
    cudaGetSymbolAddress((void**)&kh,   g_kh);
    cudaGetSymbolAddress((void**)&vh,   g_vh);

    cudaFuncSetAttribute(tc_gemm_qkv, cudaFuncAttributeMaxDynamicSharedMemorySize, GEMM_SMEM);
    cudaFuncSetAttribute(tc_gemm_o,   cudaFuncAttributeMaxDynamicSharedMemorySize, GEMM_SMEM);
    cudaFuncSetAttribute(attn_mma,    cudaFuncAttributeMaxDynamicSharedMemorySize, ATTN_SMEM);

    cvt_all<<<5 * 8192, 256>>>(x, wq, wk, wv, wo, xh, wqh, wkh, wvh, woh);

    tc_gemm_qkv<<<6144, 256, GEMM_SMEM>>>(xh, wqh, wkh, wvh,
                                          qh, kh, vh, fcos, fsin);

    attn_mma<<<dim3(Sq / 128, Bz * Hh), 256, ATTN_SMEM>>>(qh, kh, vh, atth);

    tc_gemm_o<<<2048, 256, GEMM_SMEM>>>(atth, woh, out);
}

// round 17
// speedup vs baseline: 1.2491x; 1.2491x over previous
#include <cuda_runtime.h>
#include <cuda_bf16.h>
#include <cuda_fp16.h>
#include <cstdint>
#include <math.h>

// Problem constants
constexpr int Bz  = 4;
constexpr int Sq  = 1024;
constexpr int DIM = 4096;
constexpr int Hh  = 32;
constexpr int HD  = 128;
constexpr int MM  = Bz * Sq;        // 4096 rows
constexpr float QS2 = 0.08838834764831845f * 1.4426950408889634f; // 1/sqrt(128)*log2(e)

// Scratch (static device globals)
__device__ __half g_xh[MM * DIM];
__device__ __half g_wqh[DIM * DIM];
__device__ __half g_wkh[DIM * DIM];
__device__ __half g_wvh[DIM * DIM];
__device__ __half g_woh[DIM * DIM];
__device__ __half g_atth[MM * DIM];
__device__ __half g_qh[MM * DIM];
__device__ __half g_kh[MM * DIM];
__device__ __half g_vh[MM * DIM];

// ---------------------------------------------------------------------------
// helpers
// ---------------------------------------------------------------------------
__device__ __forceinline__ uint32_t smem_u32(const void* p) {
    uint32_t a;
    asm("{ .reg .u64 t; cvta.to.shared.u64 t, %1; cvt.u32.u64 %0, t; }"
        : "=r"(a) : "l"(p));
    return a;
}
__device__ __forceinline__ void ldsm4(uint32_t* r, uint32_t addr) {
    asm volatile("ldmatrix.sync.aligned.m8n8.x4.shared.b16 {%0,%1,%2,%3}, [%4];"
        : "=r"(r[0]), "=r"(r[1]), "=r"(r[2]), "=r"(r[3]) : "r"(addr));
}
__device__ __forceinline__ void ldsm4t(uint32_t* r, uint32_t addr) {
    asm volatile("ldmatrix.sync.aligned.m8n8.x4.trans.shared.b16 {%0,%1,%2,%3}, [%4];"
        : "=r"(r[0]), "=r"(r[1]), "=r"(r[2]), "=r"(r[3]) : "r"(addr));
}
__device__ __forceinline__ void mma_f16(float* d, const uint32_t* a,
                                        uint32_t b0, uint32_t b1) {
    asm volatile(
        "mma.sync.aligned.m16n8k16.row.col.f32.f16.f16.f32 "
        "{%0,%1,%2,%3}, {%4,%5,%6,%7}, {%8,%9}, {%0,%1,%2,%3};"
        : "+f"(d[0]), "+f"(d[1]), "+f"(d[2]), "+f"(d[3])
        : "r"(a[0]), "r"(a[1]), "r"(a[2]), "r"(a[3]), "r"(b0), "r"(b1));
}
__device__ __forceinline__ float fexp2(float x) {
    float y;
    asm("ex2.approx.ftz.f32 %0, %1;" : "=f"(y) : "f"(x));
    return y;
}
__device__ __forceinline__ uint32_t packh2(float a, float b) {
    __half2 h = __floats2half2_rn(a, b);
    return *(uint32_t*)&h;
}

// ---------------------------------------------------------------------------
// fused fp32 -> fp16 conversion for 5 tensors, 1 launch, 8 elems/thread.
// ---------------------------------------------------------------------------
__global__ __launch_bounds__(256)
void cvt_all(const float* __restrict__ s0, const float* __restrict__ s1,
             const float* __restrict__ s2, const float* __restrict__ s3,
             const float* __restrict__ s4,
             __half* __restrict__ d0, __half* __restrict__ d1,
             __half* __restrict__ d2, __half* __restrict__ d3,
             __half* __restrict__ d4)
{
    const int seg = blockIdx.x >> 13;
    const int blk = blockIdx.x & 8191;
    const float* s = (seg == 0) ? s0 : (seg == 1) ? s1 : (seg == 2) ? s2
                    : (seg == 3) ? s3 : s4;
    __half* d = (seg == 0) ? d0 : (seg == 1) ? d1 : (seg == 2) ? d2
               : (seg == 3) ? d3 : d4;
    const long i = ((long)blk * 256 + threadIdx.x) * 4;
    const long j = i + 8192 * 256 * 4;
    float4 v0 = *(const float4*)(s + i);
    float4 v1 = *(const float4*)(s + j);
    *(__half2*)(d + i)     = __floats2half2_rn(v0.x, v0.y);
    *(__half2*)(d + i + 2) = __floats2half2_rn(v0.z, v0.w);
    *(__half2*)(d + j)     = __floats2half2_rn(v1.x, v1.y);
    *(__half2*)(d + j + 2) = __floats2half2_rn(v1.z, v1.w);
}

// ---------------------------------------------------------------------------
// GEMM core (legacy-HMMA pipe peak; warp tile 64x32 is the validated optimum —
// BN=64/warp 64x16 regressed 20% (ldsm-bound), R16).
// CTA 128x128, BK=32, 8 warps (2m x 4n), ldmatrix.x4, 4-stage cp.async,
// 2 CTAs/SM, one barrier per k-tile.
// ---------------------------------------------------------------------------
constexpr int BM = 128, BN = 128, BK = 32, KPAD = 40;
constexpr int A_E = BM * KPAD;
constexpr int B_E = BN * KPAD;
constexpr int STAGE_E = A_E + B_E;
constexpr int GEMM_SMEM = 4 * STAGE_E * 2;     // 81920 bytes

struct GemmCore {
    template<typename EPI>
    __device__ __forceinline__ static void run(
        const __half* Ag, const __half* Wg, char* shraw, EPI&& epi)
    {
        const uint32_t smb = smem_u32(shraw);
        const int tid  = threadIdx.x;
        const int wid  = tid >> 5;
        const int lane = tid & 31;
        const int warp_m = wid & 1;
        const int warp_n = wid >> 1;

        auto issue = [&](int kt, int st) {
            const long kof = (long)kt * BK;
            const uint32_t sbase = smb + (uint32_t)(st * STAGE_E) * 2;
#pragma unroll
            for (int q = 0; q < 2; q++) {
                const int c = tid + 256 * q;
                const int row = c >> 2, cc = (c & 3) * 8;
                const __half* s = Ag + (long)row * DIM + kof + cc;
                const uint32_t d = sbase + (uint32_t)(row * KPAD + cc) * 2;
                asm volatile("cp.async.cg.shared.global [%0], [%1], 16;" :: "r"(d), "l"(s));
            }
#pragma unroll
            for (int q = 0; q < 2; q++) {
                const int c = tid + 256 * q;
                const int row = c >> 2, cc = (c & 3) * 8;
                const __half* s = Wg + (long)row * DIM + kof + cc;
                const uint32_t d = sbase + (uint32_t)(A_E + row * KPAD + cc) * 2;
                asm volatile("cp.async.cg.shared.global [%0], [%1], 16;" :: "r"(d), "l"(s));
            }
        };

        float acc[4][4][4];
#pragma unroll
        for (int i = 0; i < 4; i++)
#pragma unroll
            for (int j = 0; j < 4; j++)
#pragma unroll
                for (int q = 0; q < 4; q++) acc[i][j][q] = 0.f;

        issue(0, 0); asm volatile("cp.async.commit_group;" ::: "memory");
        issue(1, 1); asm volatile("cp.async.commit_group;" ::: "memory");
        issue(2, 2); asm volatile("cp.async.commit_group;" ::: "memory");

        const int arow  = warp_m * 64 + (lane & 15);
        const int acol8 = (lane >> 4) << 3;
        const int brow  = warp_n * 32 + (lane & 7) + ((lane >> 4) << 3);
        const int bcol8 = ((lane >> 3) & 1) << 3;

        const int NT = DIM / BK;   // 128
        for (int t = 0; t < NT; t++) {
            asm volatile("cp.async.wait_group 2;" ::: "memory");
            __syncthreads();

            if (t + 3 < NT) issue(t + 3, (t + 3) & 3);
            asm volatile("cp.async.commit_group;" ::: "memory");

            const uint32_t base = smb + (uint32_t)((t & 3) * STAGE_E) * 2;
#pragma unroll
            for (int ks = 0; ks < 2; ks++) {
                const int kk = ks * 16;
                uint32_t af[4][4], bf[2][4];
#pragma unroll
                for (int mf = 0; mf < 4; mf++)
                    ldsm4(af[mf], base + (uint32_t)((arow + mf * 16) * KPAD + kk + acol8) * 2);
#pragma unroll
                for (int nfp = 0; nfp < 2; nfp++)
                    ldsm4(bf[nfp], base + (uint32_t)(A_E + (brow + nfp * 16) * KPAD + kk + bcol8) * 2);
#pragma unroll
                for (int mf = 0; mf < 4; mf++)
#pragma unroll
                    for (int nfp = 0; nfp < 2; nfp++) {
                        mma_f16(acc[mf][2 * nfp],     af[mf], bf[nfp][0], bf[nfp][1]);
                        mma_f16(acc[mf][2 * nfp + 1], af[mf], bf[nfp][2], bf[nfp][3]);
                    }
            }
        }
        epi(acc, warp_m, warp_n, lane);
    }
};

// ---------------------------------------------------------------------------
// Fused QKV GEMM: one launch; n-third selects weight + epilogue.
// ---------------------------------------------------------------------------
__global__ __launch_bounds__(256, 2)
void tc_gemm_qkv(const __half* __restrict__ A,
                 const __half* __restrict__ Wq, const __half* __restrict__ Wk,
                 const __half* __restrict__ Wv,
                 __half* __restrict__ qo, __half* __restrict__ ko,
                 __half* __restrict__ vo,
                 const float* __restrict__ fcos, const float* __restrict__ fsin)
{
    extern __shared__ __align__(16) char shraw[];

    const int bid = blockIdx.x;
    const int grp = bid / (8 * 96);
    const int r   = bid - grp * (8 * 96);
    const int m0  = (grp * 8 + (r & 7)) * BM;
    const int nidx = r >> 3;
    const int third = nidx >> 5;
    const int n0   = (nidx & 31) * BN;

    const __half* W = (third == 0) ? Wq : (third == 1) ? Wk : Wv;
    __half* O = (third == 0) ? qo : (third == 1) ? ko : vo;

    GemmCore::run(A + (long)m0 * DIM, W + (long)n0 * DIM, shraw,
        [&](float acc[4][4][4], int warp_m, int warp_n, int lane) {
            const int g   = lane >> 2;
            const int tig = lane & 3;
#pragma unroll
            for (int mf = 0; mf < 4; mf++) {
                const long gr0 = m0 + warp_m * 64 + mf * 16 + g;
#pragma unroll
                for (int nf = 0; nf < 4; nf++) {
                    const int gc = n0 + warp_n * 32 + nf * 8 + tig * 2;
#pragma unroll
                    for (int half = 0; half < 2; half++) {
                        const long row = gr0 + half * 8;
                        float v0 = acc[mf][nf][2 * half], v1 = acc[mf][nf][2 * half + 1];
                        float o0, o1;
                        if (third <= 1) {
                            const int s = (int)(row & (Sq - 1));
                            const int p = (gc & (HD - 1)) >> 1;
                            const float c  = fcos[s * 64 + p];
                            const float sn = fsin[s * 64 + p];
                            o0 = v0 * c - v1 * sn;
                            o1 = v0 * sn + v1 * c;
                            if (third == 0) { o0 *= QS2; o1 *= QS2; }
                        } else {
                            o0 = v0; o1 = v1;
                        }
                        *(__half2*)(O + row * DIM + gc) = __floats2half2_rn(o0, o1);
                    }
                }
            }
        });
}

// ---------------------------------------------------------------------------
// Output GEMM: out = att * wo^T, fp32 store.
// ---------------------------------------------------------------------------
__global__ __launch_bounds__(256, 2)
void tc_gemm_o(const __half* __restrict__ A, const __half* __restrict__ W,
               float* __restrict__ C)
{
    extern __shared__ __align__(16) char shraw[];

    const int bid = blockIdx.x;
    const int grp = bid >> 7;
    const int r   = bid & 127;
    const int m0  = (grp * 4 + (r & 3)) * BM;
    const int n0  = (r >> 2) * BN;

    GemmCore::run(A + (long)m0 * DIM, W + (long)n0 * DIM, shraw,
        [&](float acc[4][4][4], int warp_m, int warp_n, int lane) {
            const int g   = lane >> 2;
            const int tig = lane & 3;
#pragma unroll
            for (int mf = 0; mf < 4; mf++) {
                const long gr0 = m0 + warp_m * 64 + mf * 16 + g;
#pragma unroll
                for (int nf = 0; nf < 4; nf++) {
                    const int gc = n0 + warp_n * 32 + nf * 8 + tig * 2;
                    *(float2*)(C + gr0 * DIM + gc)       = make_float2(acc[mf][nf][0], acc[mf][nf][1]);
                    *(float2*)(C + (gr0 + 8) * DIM + gc) = make_float2(acc[mf][nf][2], acc[mf][nf][3]);
                }
            }
        });
}

// ---------------------------------------------------------------------------
// Flash attention, single-pass fp16, register-resident P,
// double-buffered cp.async K/V.  Q block 128, KV 64.
// Smem: Q + 2*(K+V) = 104448 B -> 2 CTAs/SM.
// ---------------------------------------------------------------------------
constexpr int QP = 136;
constexpr int O_Q  = 0;
constexpr int O_K0 = O_Q  + 128 * QP;
constexpr int O_V0 = O_K0 + 64 * QP;
constexpr int O_K1 = O_V0 + 64 * QP;
constexpr int O_V1 = O_K1 + 64 * QP;
constexpr int ATTN_SMEM = (O_V1 + 64 * QP) * 2;   // 104448 bytes

__global__ __launch_bounds__(256, 2)
void attn_mma(const __half* __restrict__ Qg, const __half* __restrict__ Kg,
              const __half* __restrict__ Vg, __half* __restrict__ Oh)
{
    extern __shared__ __align__(16) __half sb[];
    const uint32_t smb = smem_u32(sb);

    const int tid  = threadIdx.x;
    const int w    = tid >> 5;
    const int lane = tid & 31;
    const int g    = lane >> 2;
    const int tig  = lane & 3;

    const int qb = blockIdx.x;
    const int bh = blockIdx.y;
    const int b  = bh >> 5;
    const int h  = bh & (Hh - 1);
    const int rowbase = b * Sq + qb * 128;
    const long colbase = h * HD;

    auto issue_kv = [&](int kb, int buf) {
        const long rbase = (long)(b * Sq + kb * 64);
        const uint32_t kdst = smb + (uint32_t)((buf ? O_K1 : O_K0)) * 2;
        const uint32_t vdst = smb + (uint32_t)((buf ? O_V1 : O_V0)) * 2;
#pragma unroll
        for (int q = 0; q < 4; q++) {
            const int u = tid + 256 * q;
            const int rr = u >> 4, c8 = (u & 15) * 8;
            const __half* ks = Kg + (rbase + rr) * DIM + colbase + c8;
            const __half* vs = Vg + (rbase + rr) * DIM + colbase + c8;
            const uint32_t off = (uint32_t)(rr * QP + c8) * 2;
            asm volatile("cp.async.cg.shared.global [%0], [%1], 16;" :: "r"(kdst + off), "l"(ks));
            asm volatile("cp.async.cg.shared.global [%0], [%1], 16;" :: "r"(vdst + off), "l"(vs));
        }
    };

    // ---- load Q tile (128 x 128 fp16) ----
#pragma unroll
    for (int q = 0; q < 8; q++) {
        const int u = tid + 256 * q;
        const int rr = u >> 4, c8 = (u & 15) * 8;
        uint4 v = *(const uint4*)(Qg + (long)(rowbase + rr) * DIM + colbase + c8);
        *(uint4*)(sb + O_Q + rr * QP + c8) = v;
    }
    issue_kv(0, 0);
    asm volatile("cp.async.commit_group;" ::: "memory");
    __syncthreads();

    // ---- preload Q fragments ----
    uint32_t qf[8][4];
    {
        const int rowQ = w * 16 + (lane & 15);
        const int colH = (lane >> 4) << 3;
#pragma unroll
        for (int ks = 0; ks < 8; ks++)
            ldsm4(qf[ks], smb + (uint32_t)(O_Q + rowQ * QP + ks * 16 + colH) * 2);
    }

    float o[16][4];
#pragma unroll
    for (int i = 0; i < 16; i++)
#pragma unroll
        for (int q = 0; q < 4; q++) o[i][q] = 0.f;
    float m0 = -1e30f, m1 = -1e30f, l0 = 0.f, l1 = 0.f;

    const int browK = (lane & 7) + ((lane >> 4) << 3);
    const int bcol8 = ((lane >> 3) & 1) << 3;
    const int vrow  = (lane & 7) + (((lane >> 3) & 1) << 3);
    const int vcol8 = (lane >> 4) << 3;

    const int nkb = 2 * qb + 2;
    for (int kb = 0; kb < nkb; kb++) {
        __syncthreads();

        if (kb + 1 < nkb) issue_kv(kb + 1, (kb + 1) & 1);
        asm volatile("cp.async.commit_group;" ::: "memory");
        asm volatile("cp.async.wait_group 1;" ::: "memory");
        __syncthreads();

        const uint32_t O_K = (kb & 1) ? O_K1 : O_K0;
        const uint32_t O_V = (kb & 1) ? O_V1 : O_V0;

        // ---- S = Q K^T ----
        float s[8][4];
#pragma unroll
        for (int i = 0; i < 8; i++)
#pragma unroll
            for (int q = 0; q < 4; q++) s[i][q] = 0.f;

#pragma unroll
        for (int ks = 0; ks < 8; ks++) {
#pragma unroll
            for (int nfp = 0; nfp < 4; nfp++) {
                uint32_t kf[4];
                ldsm4(kf, smb + (uint32_t)(O_K + (browK + nfp * 16) * QP + ks * 16 + bcol8) * 2);
                mma_f16(s[2 * nfp],     qf[ks], kf[0], kf[1]);
                mma_f16(s[2 * nfp + 1], qf[ks], kf[2], kf[3]);
            }
        }

        // ---- causal mask ----
        const int r0g = qb * 128 + w * 16 + g;
        if (kb * 64 + 63 > r0g) {
            const int r1g = r0g + 8;
#pragma unroll
            for (int nf = 0; nf < 8; nf++) {
                const int c0 = kb * 64 + nf * 8 + tig * 2;
                if (c0 > r0g)     s[nf][0] = -1e30f;
                if (c0 + 1 > r0g) s[nf][1] = -1e30f;
                if (c0 > r1g)     s[nf][2] = -1e30f;
                if (c0 + 1 > r1g) s[nf][3] = -1e30f;
            }
        }

        // ---- online softmax (base-2) ----
        float rm0 = -1e30f, rm1 = -1e30f;
#pragma unroll
        for (int nf = 0; nf < 8; nf++) {
            rm0 = fmaxf(rm0, fmaxf(s[nf][0], s[nf][1]));
            rm1 = fmaxf(rm1, fmaxf(s[nf][2], s[nf][3]));
        }
        rm0 = fmaxf(rm0, __shfl_xor_sync(0xffffffffu, rm0, 1));
        rm0 = fmaxf(rm0, __shfl_xor_sync(0xffffffffu, rm0, 2));
        rm1 = fmaxf(rm1, __shfl_xor_sync(0xffffffffu, rm1, 1));
        rm1 = fmaxf(rm1, __shfl_xor_sync(0xffffffffu, rm1, 2));

        const float mn0 = fmaxf(m0, rm0), mn1 = fmaxf(m1, rm1);
        const float sc0 = fexp2(m0 - mn0), sc1 = fexp2(m1 - mn1);
        m0 = mn0; m1 = mn1;

        float rs0 = 0.f, rs1 = 0.f;
#pragma unroll
        for (int nf = 0; nf < 8; nf++) {
            s[nf][0] = fexp2(s[nf][0] - mn0);
            s[nf][1] = fexp2(s[nf][1] - mn0);
            s[nf][2] = fexp2(s[nf][2] - mn1);
            s[nf][3] = fexp2(s[nf][3] - mn1);
            rs0 += s[nf][0] + s[nf][1];
            rs1 += s[nf][2] + s[nf][3];
        }
        rs0 += __shfl_xor_sync(0xffffffffu, rs0, 1);
        rs0 += __shfl_xor_sync(0xffffffffu, rs0, 2);
        rs1 += __shfl_xor_sync(0xffffffffu, rs1, 1);
        rs1 += __shfl_xor_sync(0xffffffffu, rs1, 2);
        l0 = l0 * sc0 + rs0;
        l1 = l1 * sc1 + rs1;

#pragma unroll
        for (int nf = 0; nf < 16; nf++) {
            o[nf][0] *= sc0; o[nf][1] *= sc0;
            o[nf][2] *= sc1; o[nf][3] *= sc1;
        }

        // ---- pack P into A-fragments in registers ----
        uint32_t pf[4][4];
#pragma unroll
        for (int ks2 = 0; ks2 < 4; ks2++) {
            pf[ks2][0] = packh2(s[2 * ks2][0],     s[2 * ks2][1]);
            pf[ks2][1] = packh2(s[2 * ks2][2],     s[2 * ks2][3]);
            pf[ks2][2] = packh2(s[2 * ks2 + 1][0], s[2 * ks2 + 1][1]);
            pf[ks2][3] = packh2(s[2 * ks2 + 1][2], s[2 * ks2 + 1][3]);
        }

        // ---- O += P V ----
#pragma unroll
        for (int ks2 = 0; ks2 < 4; ks2++) {
#pragma unroll
            for (int nfp = 0; nfp < 8; nfp++) {
                uint32_t vf[4];
                ldsm4t(vf, smb + (uint32_t)(O_V + (vrow + ks2 * 16) * QP + nfp * 16 + vcol8) * 2);
                mma_f16(o[2 * nfp],     pf[ks2], vf[0], vf[1]);
                mma_f16(o[2 * nfp + 1], pf[ks2], vf[2], vf[3]);
            }
        }
    }

    // ---- epilogue ----
    const float inv0 = 1.f / l0, inv1 = 1.f / l1;
    const long gr0 = rowbase + w * 16 + g;
#pragma unroll
    for (int nf = 0; nf < 16; nf++) {
        const long gc = colbase + nf * 8 + tig * 2;
        *(__half2*)(Oh + gr0 * DIM + gc) =
            __floats2half2_rn(o[nf][0] * inv0, o[nf][1] * inv0);
        *(__half2*)(Oh + (gr0 + 8) * DIM + gc) =
            __floats2half2_rn(o[nf][2] * inv1, o[nf][3] * inv1);
    }
}

// ---------------------------------------------------------------------------
// Launch:  cvt_all -> fused qkv GEMM -> attention -> wo GEMM  (4 launches)
// ---------------------------------------------------------------------------
extern "C" void kernel_launch(void* const* d_in, const int* in_sizes, int n_in,
                              void* d_out, int out_size)
{
    const float* x    = (const float*)d_in[0];
    const float* fcos = (const float*)d_in[2];
    const float* fsin = (const float*)d_in[3];
    const float* wq   = (const float*)d_in[5];
    const float* wk   = (const float*)d_in[6];
    const float* wv   = (const float*)d_in[7];
    const float* wo   = (const float*)d_in[8];
    float* out = (float*)d_out;

    __half *xh, *wqh, *wkh, *wvh, *woh, *atth, *qh, *kh, *vh;
    cudaGetSymbolAddress((void**)&xh,   g_xh);
    cudaGetSymbolAddress((void**)&wqh,  g_wqh);
    cudaGetSymbolAddress((void**)&wkh,  g_wkh);
    cudaGetSymbolAddress((void**)&wvh,  g_wvh);
    cudaGetSymbolAddress((void**)&woh,  g_woh);
    cudaGetSymbolAddress((void**)&atth, g_atth);
    cudaGetSymbolAddress((void**)&qh,   g_qh);
    cudaGetSymbolAddress((void**)&kh,   g_kh);
    cudaGetSymbolAddress((void**)&vh,   g_vh);

    cudaFuncSetAttribute(tc_gemm_qkv, cudaFuncAttributeMaxDynamicSharedMemorySize, GEMM_SMEM);
    cudaFuncSetAttribute(tc_gemm_o,   cudaFuncAttributeMaxDynamicSharedMemorySize, GEMM_SMEM);
    cudaFuncSetAttribute(attn_mma,    cudaFuncAttributeMaxDynamicSharedMemorySize, ATTN_SMEM);

    cvt_all<<<5 * 8192, 256>>>(x, wq, wk, wv, wo, xh, wqh, wkh, wvh, woh);

    tc_gemm_qkv<<<3072, 256, GEMM_SMEM>>>(xh, wqh, wkh, wvh,
                                          qh, kh, vh, fcos, fsin);

    attn_mma<<<dim3(Sq / 128, Bz * Hh), 256, ATTN_SMEM>>>(qh, kh, vh, atth);

    tc_gemm_o<<<1024, 256, GEMM_SMEM>>>(atth, woh, out);
}